// round 1
// baseline (speedup 1.0000x reference)
#include <cuda_runtime.h>

// ThresholdEncode: out[i][2t]   = (x[i] <= th_t) && (x[i+1] >  th_t)
//                  out[i][2t+1] = (x[i] >  th_t) && (x[i+1] <= th_t)
// th_t = (t+1)/33, t in [0,32). Last row = zeros. Output [n][64] fp32.
// One thread per float4 (4 output floats = 2 thresholds). Coalesced STG.128.

__global__ void ThresholdEncode_kernel(const float* __restrict__ x,
                                       float4* __restrict__ out,
                                       int n) {
    int i = blockIdx.x * blockDim.x + threadIdx.x;
    int total = n << 4;            // n * 16 float4s
    if (i >= total) return;

    int row = i >> 4;
    int q   = i & 15;              // which float4 within the row

    float4 v = make_float4(0.f, 0.f, 0.f, 0.f);

    if (row < n - 1) {
        float xp = __ldg(&x[row]);
        float xn = __ldg(&x[row + 1]);

        const float inv33 = 1.0f / 33.0f;
        // float4 q covers thresholds t0 = 2q, t1 = 2q+1
        float th0 = (float)(2 * q + 1) * inv33;
        float th1 = (float)(2 * q + 2) * inv33;

        v.x = (xp <= th0 && xn >  th0) ? 1.0f : 0.0f;  // up(t0)
        v.y = (xp >  th0 && xn <= th0) ? 1.0f : 0.0f;  // down(t0)
        v.z = (xp <= th1 && xn >  th1) ? 1.0f : 0.0f;  // up(t1)
        v.w = (xp >  th1 && xn <= th1) ? 1.0f : 0.0f;  // down(t1)
    }

    out[i] = v;
}

extern "C" void kernel_launch(void* const* d_in, const int* in_sizes, int n_in,
                              void* d_out, int out_size) {
    const float* x = (const float*)d_in[0];
    float4* out = (float4*)d_out;
    int n = in_sizes[0];

    int total = n * 16;            // number of float4s
    int threads = 256;
    int blocks = (total + threads - 1) / threads;
    ThresholdEncode_kernel<<<blocks, threads>>>(x, out, n);
}

// round 2
// speedup vs baseline: 1.4649x; 1.4649x over previous
#include <cuda_runtime.h>

// ThresholdEncode: out[i][2t]   = (x[i] <= th_t) && (x[i+1] >  th_t)
//                  out[i][2t+1] = (x[i] >  th_t) && (x[i+1] <= th_t)
// th_t = (t+1)/33. Last row zeros. Output [n][64] fp32 = [n][16] float4.
// Grid-stride, ITER independent coalesced STG.128 per thread, streaming hint.

#define ITER 4

__global__ void ThresholdEncode_kernel(const float* __restrict__ x,
                                       float4* __restrict__ out,
                                       int n) {
    const int total  = n << 4;                       // n * 16 float4s
    const int stride = gridDim.x * blockDim.x;
    const int i0     = blockIdx.x * blockDim.x + threadIdx.x;
    const float inv33 = 1.0f / 33.0f;
    const int nm1 = n - 1;

    for (int base = i0; base < total; base += ITER * stride) {
        float4 v[ITER];
        int    idx[ITER];

        #pragma unroll
        for (int k = 0; k < ITER; k++) {
            idx[k] = base + k * stride;
            v[k] = make_float4(0.f, 0.f, 0.f, 0.f);
            if (idx[k] < total) {
                int row = idx[k] >> 4;
                int q   = idx[k] & 15;
                if (row < nm1) {
                    float xp = __ldg(&x[row]);
                    float xn = __ldg(&x[row + 1]);
                    float th0 = (float)(2 * q + 1) * inv33;
                    float th1 = (float)(2 * q + 2) * inv33;
                    v[k].x = (xp <= th0 && xn >  th0) ? 1.0f : 0.0f;
                    v[k].y = (xp >  th0 && xn <= th0) ? 1.0f : 0.0f;
                    v[k].z = (xp <= th1 && xn >  th1) ? 1.0f : 0.0f;
                    v[k].w = (xp >  th1 && xn <= th1) ? 1.0f : 0.0f;
                }
            }
        }

        #pragma unroll
        for (int k = 0; k < ITER; k++) {
            if (idx[k] < total) {
                __stcs(&out[idx[k]], v[k]);   // streaming: evict-first in L2
            }
        }
    }
}

extern "C" void kernel_launch(void* const* d_in, const int* in_sizes, int n_in,
                              void* d_out, int out_size) {
    const float* x = (const float*)d_in[0];
    float4* out = (float4*)d_out;
    int n = in_sizes[0];

    int total   = n * 16;                 // float4 count
    int threads = 256;
    int blocks  = (total + threads * ITER - 1) / (threads * ITER);
    ThresholdEncode_kernel<<<blocks, threads>>>(x, out, n);
}